// round 13
// baseline (speedup 1.0000x reference)
#include <cuda_runtime.h>
#include <cuda_bf16.h>
#include <math.h>
#include <stdint.h>

#define Bsz 2
#define Ssz 2048
#define HIDsz 1024
#define Hsz 16
#define Dsz 64
#define Msz (Bsz*Ssz)
#define BHsz (Bsz*Hsz)

// ---------------- scratch globals ----------------
__device__ float g_v[(size_t)BHsz*Ssz*Dsz];      // [B,H,S,D] fp32 (for transpose)
__device__ float g_dummy_out[(size_t)Bsz*Ssz*HIDsz];

__device__ __nv_bfloat16 g_qh[(size_t)BHsz*Ssz*Dsz], g_ql[(size_t)BHsz*Ssz*Dsz];
__device__ __nv_bfloat16 g_kh[(size_t)BHsz*Ssz*Dsz], g_kl[(size_t)BHsz*Ssz*Dsz];
__device__ __nv_bfloat16 g_vth[(size_t)BHsz*Dsz*Ssz], g_vtl[(size_t)BHsz*Dsz*Ssz]; // [bh][d][t]

__device__ __nv_bfloat16 g_xh[(size_t)Msz*HIDsz],  g_xl[(size_t)Msz*HIDsz];
__device__ __nv_bfloat16 g_wh[(size_t)3*HIDsz*HIDsz], g_wl[(size_t)3*HIDsz*HIDsz];
__device__ __nv_bfloat16 g_owh[(size_t)HIDsz*HIDsz],  g_owl[(size_t)HIDsz*HIDsz];
__device__ __nv_bfloat16 g_aoh[(size_t)Msz*HIDsz], g_aol[(size_t)Msz*HIDsz];
__device__ float g_bqkv[3*HIDsz];
__device__ float g_scale[Dsz];

// ---------------- helpers ----------------
__device__ __forceinline__ uint32_t smem_u32(const void* p) {
    uint32_t a;
    asm("{ .reg .u64 t; cvta.to.shared.u64 t, %1; cvt.u32.u64 %0, t; }" : "=r"(a) : "l"(p));
    return a;
}
__device__ __forceinline__ void cp16(uint32_t dst, const void* src) {
    asm volatile("cp.async.cg.shared.global [%0], [%1], 16;" :: "r"(dst), "l"(src));
}
__device__ __forceinline__ void ldsm4(uint32_t* r, uint32_t a) {
    asm volatile("ldmatrix.sync.aligned.m8n8.x4.shared.b16 {%0,%1,%2,%3}, [%4];"
        : "=r"(r[0]), "=r"(r[1]), "=r"(r[2]), "=r"(r[3]) : "r"(a));
}
__device__ __forceinline__ void mma_bf16(float* c, const uint32_t* a, const uint32_t* b) {
    asm volatile("mma.sync.aligned.m16n8k16.row.col.f32.bf16.bf16.f32 "
        "{%0,%1,%2,%3}, {%4,%5,%6,%7}, {%8,%9}, {%0,%1,%2,%3};"
        : "+f"(c[0]), "+f"(c[1]), "+f"(c[2]), "+f"(c[3])
        : "r"(a[0]), "r"(a[1]), "r"(a[2]), "r"(a[3]), "r"(b[0]), "r"(b[1]));
}
__device__ __forceinline__ uint32_t pack_bf16x2(float lo, float hi) {
    uint32_t r; asm("cvt.rn.bf16x2.f32 %0, %1, %2;" : "=r"(r) : "f"(hi), "f"(lo)); return r;
}
__device__ __forceinline__ float2 bf16x2_to_f2(uint32_t u) {
    float2 r;
    r.x = __uint_as_float(u << 16);
    r.y = __uint_as_float(u & 0xffff0000u);
    return r;
}

// ---------------- prepack: all fp32 -> bf16 hi/lo in ONE kernel -----------
#define N4_X (Msz*HIDsz/4)
#define N4_W (HIDsz*HIDsz/4)
struct alignas(8) B4 { __nv_bfloat16 v[4]; };

__global__ void __launch_bounds__(256) cvt_all_kernel(
    const float* __restrict__ x,  const float* __restrict__ qw,
    const float* __restrict__ kw, const float* __restrict__ vw,
    const float* __restrict__ ow)
{
    size_t i = (size_t)blockIdx.x * 256 + threadIdx.x;
    if (i >= (size_t)N4_X + 4*(size_t)N4_W) return;
    const float* src; __nv_bfloat16 *hi, *lo; size_t j;
    if (i < N4_X) { src = x; hi = g_xh; lo = g_xl; j = i; }
    else {
        size_t k = i - N4_X; int r = (int)(k / N4_W); j = k % N4_W;
        if (r == 0)      { src = qw; hi = g_wh;                        lo = g_wl; }
        else if (r == 1) { src = kw; hi = g_wh + (size_t)HIDsz*HIDsz;  lo = g_wl + (size_t)HIDsz*HIDsz; }
        else if (r == 2) { src = vw; hi = g_wh + 2*(size_t)HIDsz*HIDsz; lo = g_wl + 2*(size_t)HIDsz*HIDsz; }
        else             { src = ow; hi = g_owh;                       lo = g_owl; }
    }
    float4 v = ((const float4*)src)[j];
    B4 h, l;
    float xs[4] = {v.x, v.y, v.z, v.w};
    #pragma unroll
    for (int t = 0; t < 4; ++t) {
        __nv_bfloat16 hb = __float2bfloat16_rn(xs[t]);
        h.v[t] = hb;
        l.v[t] = __float2bfloat16_rn(xs[t] - __bfloat162float(hb));
    }
    *(B4*)(hi + 4*j) = h;
    *(B4*)(lo + 4*j) = l;
}

__global__ void pack_misc_kernel(const float* qb, const float* kb, const float* vb,
                                 const float* scaling)
{
    int i = blockIdx.x * 256 + threadIdx.x;
    if (i < 1024)       g_bqkv[i] = qb[i];
    else if (i < 2048)  g_bqkv[i] = kb[i-1024];
    else if (i < 3072)  g_bqkv[i] = vb[i-2048];
    if (i < 64) {
        float sc = scaling[i];
        float sp = (sc > 20.f) ? sc : log1pf(expf(sc));
        g_scale[i] = sp * (1.442695040888963f * 0.125f);
    }
}

// ---------------- HMMA GEMM mainloop (dense projections) ----------------
#define PITCH   40
#define TILE_B  (128*PITCH*2)
#define STAGE_B (4*TILE_B)
#define GEMM_SMEM (2*STAGE_B)

__device__ __forceinline__ void gemm128(
    uint32_t smem_base,
    const __nv_bfloat16* __restrict__ Ah, const __nv_bfloat16* __restrict__ Al,
    const __nv_bfloat16* __restrict__ Bh, const __nv_bfloat16* __restrict__ Bl,
    int mBase, int nBase, float acc[4][4][4])
{
    const int tid  = threadIdx.x;
    const int wid  = tid >> 5, lane = tid & 31;
    const int warpM = wid >> 2, warpN = wid & 3;

    #define LOAD_CHUNK(ch) do {                                                 \
        const int st_ = (ch) & 1; const int kt_ = (ch) * 32;                    \
        uint32_t sb_ = smem_base + st_ * STAGE_B;                               \
        _Pragma("unroll")                                                       \
        for (int t_ = 0; t_ < 4; ++t_) {                                        \
            const __nv_bfloat16* src_ = t_==0?Ah:t_==1?Al:t_==2?Bh:Bl;          \
            int rowBase_ = (t_ < 2) ? mBase : nBase;                            \
            _Pragma("unroll")                                                   \
            for (int u_ = 0; u_ < 2; ++u_) {                                    \
                int idx_ = u_*256 + tid;                                        \
                int row_ = idx_ >> 2, cc_ = idx_ & 3;                           \
                cp16(sb_ + t_*TILE_B + row_*(PITCH*2) + cc_*16,                 \
                     src_ + (size_t)(rowBase_+row_)*HIDsz + kt_ + cc_*8);       \
            }                                                                   \
        }                                                                       \
        asm volatile("cp.async.commit_group;" ::: "memory");                    \
    } while (0)

    LOAD_CHUNK(0);
    for (int ch = 0; ch < 32; ++ch) {
        if (ch < 31) {
            LOAD_CHUNK(ch+1);
            asm volatile("cp.async.wait_group 1;" ::: "memory");
        } else {
            asm volatile("cp.async.wait_group 0;" ::: "memory");
        }
        __syncthreads();
        uint32_t sb = smem_base + (ch & 1) * STAGE_B;

        #pragma unroll
        for (int ks = 0; ks < 2; ++ks) {
            uint32_t ah[4][4], al[4][4], bh[2][4], bl[2][4];
            int acol = ks*32 + 16*(lane >> 4);
            int arow = warpM*64 + (lane & 15);
            #pragma unroll
            for (int mt = 0; mt < 4; ++mt)
                ldsm4(ah[mt], sb + 0*TILE_B + (arow + mt*16)*(PITCH*2) + acol);
            #pragma unroll
            for (int mt = 0; mt < 4; ++mt)
                ldsm4(al[mt], sb + 1*TILE_B + (arow + mt*16)*(PITCH*2) + acol);
            int bcol  = ks*32 + 16*((lane >> 3) & 1);
            int brow  = warpN*32 + (lane & 7) + ((lane >> 4) << 3);
            #pragma unroll
            for (int np = 0; np < 2; ++np) {
                ldsm4(bh[np], sb + 2*TILE_B + (brow + np*16)*(PITCH*2) + bcol);
                ldsm4(bl[np], sb + 3*TILE_B + (brow + np*16)*(PITCH*2) + bcol);
            }
            #pragma unroll
            for (int mt = 0; mt < 4; ++mt)
                #pragma unroll
                for (int nt = 0; nt < 4; ++nt) {
                    const uint32_t* bhp = &bh[nt >> 1][(nt & 1) * 2];
                    const uint32_t* blp = &bl[nt >> 1][(nt & 1) * 2];
                    mma_bf16(acc[mt][nt], ah[mt], bhp);
                    mma_bf16(acc[mt][nt], al[mt], bhp);
                    mma_bf16(acc[mt][nt], ah[mt], blp);
                }
        }
        __syncthreads();
    }
    #undef LOAD_CHUNK
}

// ---------------- QKV projection (HMMA) ----------------
__global__ void __launch_bounds__(256) qkv_mma_kernel()
{
    extern __shared__ char smem[];
    uint32_t smem_base = smem_u32(smem);
    const int tid = threadIdx.x;
    const int wid = tid >> 5, lane = tid & 31;
    const int warpM = wid >> 2, warpN = wid & 3;
    const int nBase = blockIdx.x * 128;
    const int mBase = blockIdx.y * 128;

    float acc[4][4][4] = {};
    gemm128(smem_base, g_xh, g_xl, g_wh, g_wl, mBase, nBase, acc);

    const int which = nBase >> 10;

    #pragma unroll
    for (int mt = 0; mt < 4; ++mt) {
        int m0 = mBase + warpM*64 + mt*16 + (lane >> 2);
        #pragma unroll
        for (int nt = 0; nt < 4; ++nt) {
            int nG = nBase + warpN*32 + nt*8 + 2*(lane & 3);
            int nl = nG & 1023, h = nl >> 6, d = nl & 63;
            float s0 = (which == 0) ? g_scale[d] : 1.f;
            float s1 = (which == 0) ? g_scale[d+1] : 1.f;
            float b0 = g_bqkv[nG], b1 = g_bqkv[nG+1];
            #pragma unroll
            for (int half = 0; half < 2; ++half) {
                int m = m0 + half*8;
                int b = m >> 11, s = m & 2047;
                float v0 = (acc[mt][nt][half*2+0] + b0) * s0;
                float v1 = (acc[mt][nt][half*2+1] + b1) * s1;
                size_t off = ((size_t)(b*Hsz + h)*Ssz + s)*Dsz + d;
                if (which == 2) {
                    *(float2*)&g_v[off] = make_float2(v0, v1);
                } else {
                    uint32_t hh = pack_bf16x2(v0, v1);
                    float2 bb = bf16x2_to_f2(hh);
                    uint32_t ll = pack_bf16x2(v0 - bb.x, v1 - bb.y);
                    if (which == 0) {
                        *(uint32_t*)&g_qh[off] = hh;
                        *(uint32_t*)&g_ql[off] = ll;
                    } else {
                        *(uint32_t*)&g_kh[off] = hh;
                        *(uint32_t*)&g_kl[off] = ll;
                    }
                }
            }
        }
    }
}

// ---------------- V transpose + split ----------------
__global__ void __launch_bounds__(256) vt_cvt_kernel()
{
    __shared__ float ts[128][65];
    const int bh = blockIdx.y, tB = blockIdx.x, tid = threadIdx.x;
    const float* src = g_v + ((size_t)bh*Ssz + tB*128)*Dsz;
    #pragma unroll
    for (int u = 0; u < 8; ++u) {
        int idx = u*256 + tid;
        int row = idx >> 4, c4 = (idx & 15) << 2;
        float4 v = *(const float4*)(src + row*64 + c4);
        ts[row][c4]=v.x; ts[row][c4+1]=v.y; ts[row][c4+2]=v.z; ts[row][c4+3]=v.w;
    }
    __syncthreads();
    #pragma unroll
    for (int u = 0; u < 16; ++u) {
        int idx = u*256 + tid;
        int d = idx >> 6, tp = idx & 63;
        float f0 = ts[tp*2][d], f1 = ts[tp*2+1][d];
        uint32_t h = pack_bf16x2(f0, f1);
        float2 hb = bf16x2_to_f2(h);
        uint32_t l = pack_bf16x2(f0 - hb.x, f1 - hb.y);
        size_t off = ((size_t)bh*Dsz + d)*Ssz + tB*128 + tp*2;
        *(uint32_t*)&g_vth[off] = h;
        *(uint32_t*)&g_vtl[off] = l;
    }
}

// ---------------- HMMA flash attention (two-pass, k-tile 64, 2 CTA/SM) ----
#define QH_OFF 0
#define QL_OFF 18432
#define ST_OFF 36864
#define ST_STRIDE 36864
#define KH_OFF 0
#define KL_OFF 9216
#define VH_OFF 18432
#define VL_OFF 27648
#define ATTN_SMEM 110592

__global__ void __launch_bounds__(256, 2) attn_mma_kernel(float* __restrict__ attnp)
{
    extern __shared__ char sm[];
    const uint32_t sb = smem_u32(sm);
    const int tid = threadIdx.x, wid = tid >> 5, lane = tid & 31;
    const int gid = lane >> 2, qc = lane & 3;
    const int qb = (int)(gridDim.x - 1) - (int)blockIdx.x;   // heavy first
    const int bh = blockIdx.y;
    const int qrow0 = qb * 128;
    const int ntb = 2*qb + 2;                                // 64-wide k tiles

    const __nv_bfloat16* qhg = g_qh + ((size_t)bh*Ssz + qrow0)*Dsz;
    const __nv_bfloat16* qlg = g_ql + ((size_t)bh*Ssz + qrow0)*Dsz;
    const __nv_bfloat16* khg = g_kh + (size_t)bh*Ssz*Dsz;
    const __nv_bfloat16* klg = g_kl + (size_t)bh*Ssz*Dsz;
    const __nv_bfloat16* vhg = g_vth + (size_t)bh*Dsz*Ssz;
    const __nv_bfloat16* vlg = g_vtl + (size_t)bh*Dsz*Ssz;
    float* aBase = attnp ? (attnp + (size_t)bh*Ssz*Ssz) : (float*)0;

    const int r0 = wid*16 + gid, r1 = r0 + 8;

    // Q tile + K tile 0
    #pragma unroll
    for (int u = 0; u < 4; ++u) {
        int idx = u*256 + tid, row = idx >> 3, c = idx & 7;
        cp16(sb + QH_OFF + row*144 + c*16, qhg + (size_t)row*64 + c*8);
        cp16(sb + QL_OFF + row*144 + c*16, qlg + (size_t)row*64 + c*8);
    }
    #pragma unroll
    for (int u = 0; u < 2; ++u) {
        int idx = u*256 + tid, row = idx >> 3, c = idx & 7;
        cp16(sb + ST_OFF + KH_OFF + row*144 + c*16, khg + (size_t)row*64 + c*8);
        cp16(sb + ST_OFF + KL_OFF + row*144 + c*16, klg + (size_t)row*64 + c*8);
    }
    asm volatile("cp.async.commit_group;" ::: "memory");

    float rm0 = -INFINITY, rm1 = -INFINITY, rs0 = 0.f, rs1 = 0.f;
    uint32_t qfh[4][4], qfl[4][4];

    // ================= PASS 1: stats (K only) =================
    for (int tb = 0; tb < ntb; ++tb) {
        if (tb < ntb-1) {
            const uint32_t bs2 = sb + ST_OFF + ((tb+1) & 1) * ST_STRIDE;
            const int t0 = (tb+1) * 64;
            #pragma unroll
            for (int u = 0; u < 2; ++u) {
                int idx = u*256 + tid, row = idx >> 3, c = idx & 7;
                cp16(bs2 + KH_OFF + row*144 + c*16, khg + (size_t)(t0+row)*64 + c*8);
                cp16(bs2 + KL_OFF + row*144 + c*16, klg + (size_t)(t0+row)*64 + c*8);
            }
            asm volatile("cp.async.commit_group;" ::: "memory");
            asm volatile("cp.async.wait_group 1;" ::: "memory");
        } else {
            asm volatile("cp.async.wait_group 0;" ::: "memory");
        }
        __syncthreads();

        if (tb == 0) {
            #pragma unroll
            for (int ks = 0; ks < 4; ++ks) {
                uint32_t a = sb + QH_OFF + (wid*16 + (lane & 15))*144 + ks*32 + 16*(lane >> 4);
                ldsm4(qfh[ks], a);
                ldsm4(qfl[ks], a + (QL_OFF - QH_OFF));
            }
        }
        const uint32_t bs = sb + ST_OFF + (tb & 1) * ST_STRIDE;

        float accS[8][4];
        #pragma unroll
        for (int nt = 0; nt < 8; ++nt)
            accS[nt][0] = accS[nt][1] = accS[nt][2] = accS[nt][3] = 0.f;

        #pragma unroll
        for (int ks = 0; ks < 4; ++ks) {
            uint32_t kfh[4][4], kfl[4][4];
            #pragma unroll
            for (int t4 = 0; t4 < 4; ++t4) {
                uint32_t addr = bs + KH_OFF
                    + (t4*16 + (lane & 7) + ((lane >> 4) << 3))*144
                    + ks*32 + 16*((lane >> 3) & 1);
                ldsm4(kfh[t4], addr);
                ldsm4(kfl[t4], addr + (KL_OFF - KH_OFF));
            }
            #pragma unroll
            for (int t4 = 0; t4 < 4; ++t4)
                #pragma unroll
                for (int sub = 0; sub < 2; ++sub) {
                    int nt = t4*2 + sub;
                    mma_bf16(accS[nt], qfh[ks], &kfh[t4][sub*2]);
                    mma_bf16(accS[nt], qfl[ks], &kfh[t4][sub*2]);
                    mma_bf16(accS[nt], qfh[ks], &kfl[t4][sub*2]);
                }
        }
        if (tb >= ntb-2) {   // diagonal-overlapping tiles
            #pragma unroll
            for (int nt = 0; nt < 8; ++nt) {
                int c0 = tb*64 + nt*8 + qc*2;
                if (c0     > qrow0 + r0) accS[nt][0] = -INFINITY;
                if (c0 + 1 > qrow0 + r0) accS[nt][1] = -INFINITY;
                if (c0     > qrow0 + r1) accS[nt][2] = -INFINITY;
                if (c0 + 1 > qrow0 + r1) accS[nt][3] = -INFINITY;
            }
        }
        float m0 = -INFINITY, m1 = -INFINITY;
        #pragma unroll
        for (int nt = 0; nt < 8; ++nt) {
            m0 = fmaxf(m0, fmaxf(accS[nt][0], accS[nt][1]));
            m1 = fmaxf(m1, fmaxf(accS[nt][2], accS[nt][3]));
        }
        m0 = fmaxf(m0, __shfl_xor_sync(0xffffffffu, m0, 1));
        m0 = fmaxf(m0, __shfl_xor_sync(0xffffffffu, m0, 2));
        m1 = fmaxf(m1, __shfl_xor_sync(0xffffffffu, m1, 1));
        m1 = fmaxf(m1, __shfl_xor_sync(0xffffffffu, m1, 2));
        float nm0 = fmaxf(rm0, m0), nm1 = fmaxf(rm1, m1);
        float f0 = __expf(rm0 - nm0), f1 = __expf(rm1 - nm1);
        float s0 = 0.f, s1 = 0.f;
        #pragma unroll
        for (int nt = 0; nt < 8; ++nt) {
            s0 += __expf(accS[nt][0] - nm0) + __expf(accS[nt][1] - nm0);
            s1 += __expf(accS[nt][2] - nm1) + __expf(accS[nt][3] - nm1);
        }
        s0 += __shfl_xor_sync(0xffffffffu, s0, 1);
        s0 += __shfl_xor_sync(0xffffffffu, s0, 2);
        s1 += __shfl_xor_sync(0xffffffffu, s1, 1);
        s1 += __shfl_xor_sync(0xffffffffu, s1, 2);
        rs0 = rs0*f0 + s0;  rs1 = rs1*f1 + s1;
        rm0 = nm0;          rm1 = nm1;
        __syncthreads();
    }

    const float inv0 = 1.f / rs0, inv1 = 1.f / rs1;
    float accO[8][4] = {};

    // prime pass-2 tile 0 (K + V)
    #pragma unroll
    for (int u = 0; u < 2; ++u) {
        int idx = u*256 + tid, row = idx >> 3, c = idx & 7;
        cp16(sb + ST_OFF + KH_OFF + row*144 + c*16, khg + (size_t)row*64 + c*8);
        cp16(sb + ST_OFF + KL_OFF + row*144 + c*16, klg + (size_t)row*64 + c*8);
    }
    #pragma unroll
    for (int u = 0; u < 2; ++u) {
        int idx = u*256 + tid, d = idx >> 3, c = idx & 7;
        cp16(sb + ST_OFF + VH_OFF + d*144 + c*16, vhg + (size_t)d*Ssz + c*8);
        cp16(sb + ST_OFF + VL_OFF + d*144 + c*16, vlg + (size_t)d*Ssz + c*8);
    }
    asm volatile("cp.async.commit_group;" ::: "memory");

    // ================= PASS 2: probs + PV =================
    for (int tb = 0; tb < ntb; ++tb) {
        if (tb < ntb-1) {
            const uint32_t bs2 = sb + ST_OFF + ((tb+1) & 1) * ST_STRIDE;
            const int t0 = (tb+1) * 64;
            #pragma unroll
            for (int u = 0; u < 2; ++u) {
                int idx = u*256 + tid, row = idx >> 3, c = idx & 7;
                cp16(bs2 + KH_OFF + row*144 + c*16, khg + (size_t)(t0+row)*64 + c*8);
                cp16(bs2 + KL_OFF + row*144 + c*16, klg + (size_t)(t0+row)*64 + c*8);
            }
            #pragma unroll
            for (int u = 0; u < 2; ++u) {
                int idx = u*256 + tid, d = idx >> 3, c = idx & 7;
                cp16(bs2 + VH_OFF + d*144 + c*16, vhg + (size_t)d*Ssz + t0 + c*8);
                cp16(bs2 + VL_OFF + d*144 + c*16, vlg + (size_t)d*Ssz + t0 + c*8);
            }
            asm volatile("cp.async.commit_group;" ::: "memory");
            asm volatile("cp.async.wait_group 1;" ::: "memory");
        } else {
            asm volatile("cp.async.wait_group 0;" ::: "memory");
        }
        __syncthreads();
        const uint32_t bs = sb + ST_OFF + (tb & 1) * ST_STRIDE;

        float accS[8][4];
        #pragma unroll
        for (int nt = 0; nt < 8; ++nt)
            accS[nt][0] = accS[nt][1] = accS[nt][2] = accS[nt][3] = 0.f;

        #pragma unroll
        for (int ks = 0; ks < 4; ++ks) {
            uint32_t kfh[4][4], kfl[4][4];
            #pragma unroll
            for (int t4 = 0; t4 < 4; ++t4) {
                uint32_t addr = bs + KH_OFF
                    + (t4*16 + (lane & 7) + ((lane >> 4) << 3))*144
                    + ks*32 + 16*((lane >> 3) & 1);
                ldsm4(kfh[t4], addr);
                ldsm4(kfl[t4], addr + (KL_OFF - KH_OFF));
            }
            #pragma unroll
            for (int t4 = 0; t4 < 4; ++t4)
                #pragma unroll
                for (int sub = 0; sub < 2; ++sub) {
                    int nt = t4*2 + sub;
                    mma_bf16(accS[nt], qfh[ks], &kfh[t4][sub*2]);
                    mma_bf16(accS[nt], qfl[ks], &kfh[t4][sub*2]);
                    mma_bf16(accS[nt], qfh[ks], &kfl[t4][sub*2]);
                }
        }
        if (tb >= ntb-2) {
            #pragma unroll
            for (int nt = 0; nt < 8; ++nt) {
                int c0 = tb*64 + nt*8 + qc*2;
                if (c0     > qrow0 + r0) accS[nt][0] = -INFINITY;
                if (c0 + 1 > qrow0 + r0) accS[nt][1] = -INFINITY;
                if (c0     > qrow0 + r1) accS[nt][2] = -INFINITY;
                if (c0 + 1 > qrow0 + r1) accS[nt][3] = -INFINITY;
            }
        }

        // final normalized probabilities
        #pragma unroll
        for (int nt = 0; nt < 8; ++nt) {
            accS[nt][0] = __expf(accS[nt][0] - rm0) * inv0;
            accS[nt][1] = __expf(accS[nt][1] - rm0) * inv0;
            accS[nt][2] = __expf(accS[nt][2] - rm1) * inv1;
            accS[nt][3] = __expf(accS[nt][3] - rm1) * inv1;
        }
        if (aBase) {
            float* rp0 = aBase + (size_t)(qrow0 + r0)*Ssz + tb*64;
            float* rp1 = rp0 + (size_t)8*Ssz;
            #pragma unroll
            for (int nt = 0; nt < 8; ++nt) {
                int col = nt*8 + qc*2;
                *(float2*)(rp0 + col) = make_float2(accS[nt][0], accS[nt][1]);
                *(float2*)(rp1 + col) = make_float2(accS[nt][2], accS[nt][3]);
            }
        }

        // O += P V (split P in registers)
        #pragma unroll
        for (int j = 0; j < 4; ++j) {
            uint32_t pah[4], pal[4];
            {
                float c0 = accS[2*j][0],   c1 = accS[2*j][1];
                float c2 = accS[2*j][2],   c3 = accS[2*j][3];
                float d0 = accS[2*j+1][0], d1 = accS[2*j+1][1];
                float d2 = accS[2*j+1][2], d3 = accS[2*j+1][3];
                pah[0] = pack_bf16x2(c0, c1);  pah[1] = pack_bf16x2(c2, c3);
                pah[2] = pack_bf16x2(d0, d1);  pah[3] = pack_bf16x2(d2, d3);
                float2 bb;
                bb = bf16x2_to_f2(pah[0]); pal[0] = pack_bf16x2(c0-bb.x, c1-bb.y);
                bb = bf16x2_to_f2(pah[1]); pal[1] = pack_bf16x2(c2-bb.x, c3-bb.y);
                bb = bf16x2_to_f2(pah[2]); pal[2] = pack_bf16x2(d0-bb.x, d1-bb.y);
                bb = bf16x2_to_f2(pah[3]); pal[3] = pack_bf16x2(d2-bb.x, d3-bb.y);
            }
            uint32_t vfh[4][4], vfl[4][4];
            #pragma unroll
            for (int np = 0; np < 4; ++np) {
                uint32_t addr = bs + VH_OFF
                    + (np*16 + (lane & 7) + ((lane >> 4) << 3))*144
                    + j*32 + 16*((lane >> 3) & 1);
                ldsm4(vfh[np], addr);
                ldsm4(vfl[np], addr + (VL_OFF - VH_OFF));
            }
            #pragma unroll
            for (int np = 0; np < 4; ++np)
                #pragma unroll
                for (int sub = 0; sub < 2; ++sub) {
                    int nd = np*2 + sub;
                    mma_bf16(accO[nd], pah, &vfh[np][sub*2]);
                    mma_bf16(accO[nd], pal, &vfh[np][sub*2]);
                    mma_bf16(accO[nd], pah, &vfl[np][sub*2]);
                }
        }
        __syncthreads();
    }

    // zero upper-triangle tiles (64-wide)
    if (aBase) {
        const float4 z4 = make_float4(0.f, 0.f, 0.f, 0.f);
        for (int tb2 = ntb; tb2 < Ssz/64; ++tb2) {
            float* tp = aBase + (size_t)qrow0*Ssz + tb2*64;
            #pragma unroll
            for (int u = 0; u < 8; ++u) {
                int idx = u*256 + tid;
                int row = idx >> 4, c = (idx & 15) << 2;
                *(float4*)(tp + (size_t)row*Ssz + c) = z4;
            }
        }
    }

    // write O as bf16 hi/lo planes (consumed directly by oproj)
    const int b = bh >> 4, h = bh & 15;
    int s0r = qrow0 + r0, s1r = qrow0 + r1;
    #pragma unroll
    for (int nd = 0; nd < 8; ++nd) {
        int d = nd*8 + qc*2;
        {
            float v0 = accO[nd][0], v1 = accO[nd][1];
            uint32_t hh = pack_bf16x2(v0, v1);
            float2 bb = bf16x2_to_f2(hh);
            uint32_t ll = pack_bf16x2(v0 - bb.x, v1 - bb.y);
            size_t off = ((size_t)(b*Ssz + s0r))*HIDsz + h*64 + d;
            *(uint32_t*)&g_aoh[off] = hh;
            *(uint32_t*)&g_aol[off] = ll;
        }
        {
            float v0 = accO[nd][2], v1 = accO[nd][3];
            uint32_t hh = pack_bf16x2(v0, v1);
            float2 bb = bf16x2_to_f2(hh);
            uint32_t ll = pack_bf16x2(v0 - bb.x, v1 - bb.y);
            size_t off = ((size_t)(b*Ssz + s1r))*HIDsz + h*64 + d;
            *(uint32_t*)&g_aoh[off] = hh;
            *(uint32_t*)&g_aol[off] = ll;
        }
    }
}

// ---------------- output projection (HMMA) ----------------
__global__ void __launch_bounds__(256) oproj_mma_kernel(
    const float* __restrict__ ob, float* __restrict__ outp)
{
    extern __shared__ char smem[];
    uint32_t smem_base = smem_u32(smem);
    const int tid = threadIdx.x;
    const int wid = tid >> 5, lane = tid & 31;
    const int warpM = wid >> 2, warpN = wid & 3;
    const int nBase = blockIdx.x * 128;
    const int mBase = blockIdx.y * 128;

    float acc[4][4][4] = {};
    gemm128(smem_base, g_aoh, g_aol, g_owh, g_owl, mBase, nBase, acc);

    #pragma unroll
    for (int mt = 0; mt < 4; ++mt) {
        int m0 = mBase + warpM*64 + mt*16 + (lane >> 2);
        #pragma unroll
        for (int nt = 0; nt < 4; ++nt) {
            int n = nBase + warpN*32 + nt*8 + 2*(lane & 3);
            float b0 = ob[n], b1 = ob[n+1];
            #pragma unroll
            for (int half = 0; half < 2; ++half) {
                int m = m0 + half*8;
                *(float2*)&outp[(size_t)m*HIDsz + n] = make_float2(
                    acc[mt][nt][half*2+0] + b0, acc[mt][nt][half*2+1] + b1);
            }
        }
    }
}

// ---------------- launch ----------------
extern "C" void kernel_launch(void* const* d_in, const int* in_sizes, int n_in,
                              void* d_out, int out_size)
{
    const float* x       = (const float*)d_in[0];
    const float* scaling = (const float*)d_in[2];
    const float* qb = (const float*)d_in[4];
    const float* qw = (const float*)d_in[3];
    const float* kw = (const float*)d_in[5];
    const float* kb = (const float*)d_in[6];
    const float* vw = (const float*)d_in[7];
    const float* vb = (const float*)d_in[8];
    const float* ow = (const float*)d_in[9];
    const float* ob = (const float*)d_in[10];

    const long long OUT_N  = (long long)Bsz*Ssz*HIDsz;
    const long long ATTN_N = (long long)Bsz*Hsz*Ssz*Ssz;

    float* outp  = (float*)d_out;
    float* attnp = 0;
    if ((long long)out_size >= OUT_N + ATTN_N) {
        attnp = (float*)d_out + OUT_N;
    } else if ((long long)out_size == ATTN_N) {
        attnp = (float*)d_out;
        void* p = 0;
        cudaGetSymbolAddress(&p, g_dummy_out);
        outp = (float*)p;
    }

    cudaFuncSetAttribute(qkv_mma_kernel, cudaFuncAttributeMaxDynamicSharedMemorySize, GEMM_SMEM);
    cudaFuncSetAttribute(oproj_mma_kernel, cudaFuncAttributeMaxDynamicSharedMemorySize, GEMM_SMEM);
    cudaFuncSetAttribute(attn_mma_kernel, cudaFuncAttributeMaxDynamicSharedMemorySize, ATTN_SMEM);

    const int NTOT = N4_X + 4*N4_W;
    cvt_all_kernel<<<(NTOT+255)/256, 256>>>(x, qw, kw, vw, ow);     // 0
    pack_misc_kernel<<<12, 256>>>(qb, kb, vb, scaling);             // 1
    qkv_mma_kernel<<<dim3(24, 32), 256, GEMM_SMEM>>>();             // 2
    vt_cvt_kernel<<<dim3(16, 32), 256>>>();                         // 3
    attn_mma_kernel<<<dim3(16, 32), 256, ATTN_SMEM>>>(attnp);       // 4
    oproj_mma_kernel<<<dim3(HIDsz/128, Msz/128), 256, GEMM_SMEM>>>(ob, outp); // 5
}

// round 14
// speedup vs baseline: 1.0860x; 1.0860x over previous
#include <cuda_runtime.h>
#include <cuda_bf16.h>
#include <math.h>
#include <stdint.h>

#define Bsz 2
#define Ssz 2048
#define HIDsz 1024
#define Hsz 16
#define Dsz 64
#define Msz (Bsz*Ssz)
#define BHsz (Bsz*Hsz)

// ---------------- scratch globals ----------------
__device__ float g_dummy_out[(size_t)Bsz*Ssz*HIDsz];

__device__ __nv_bfloat16 g_qh[(size_t)BHsz*Ssz*Dsz], g_ql[(size_t)BHsz*Ssz*Dsz];
__device__ __nv_bfloat16 g_kh[(size_t)BHsz*Ssz*Dsz], g_kl[(size_t)BHsz*Ssz*Dsz];
__device__ __nv_bfloat16 g_vth[(size_t)BHsz*Dsz*Ssz], g_vtl[(size_t)BHsz*Dsz*Ssz]; // [bh][d][t]

__device__ __nv_bfloat16 g_xh[(size_t)Msz*HIDsz],  g_xl[(size_t)Msz*HIDsz];
__device__ __nv_bfloat16 g_wh[(size_t)3*HIDsz*HIDsz], g_wl[(size_t)3*HIDsz*HIDsz];
__device__ __nv_bfloat16 g_owh[(size_t)HIDsz*HIDsz],  g_owl[(size_t)HIDsz*HIDsz];
__device__ __nv_bfloat16 g_aoh[(size_t)Msz*HIDsz], g_aol[(size_t)Msz*HIDsz];
__device__ float g_bqkv[3*HIDsz];
__device__ float g_scale[Dsz];

// ---------------- helpers ----------------
__device__ __forceinline__ uint32_t smem_u32(const void* p) {
    uint32_t a;
    asm("{ .reg .u64 t; cvta.to.shared.u64 t, %1; cvt.u32.u64 %0, t; }" : "=r"(a) : "l"(p));
    return a;
}
__device__ __forceinline__ void cp16(uint32_t dst, const void* src) {
    asm volatile("cp.async.cg.shared.global [%0], [%1], 16;" :: "r"(dst), "l"(src));
}
__device__ __forceinline__ void ldsm4(uint32_t* r, uint32_t a) {
    asm volatile("ldmatrix.sync.aligned.m8n8.x4.shared.b16 {%0,%1,%2,%3}, [%4];"
        : "=r"(r[0]), "=r"(r[1]), "=r"(r[2]), "=r"(r[3]) : "r"(a));
}
__device__ __forceinline__ void mma_bf16(float* c, const uint32_t* a, const uint32_t* b) {
    asm volatile("mma.sync.aligned.m16n8k16.row.col.f32.bf16.bf16.f32 "
        "{%0,%1,%2,%3}, {%4,%5,%6,%7}, {%8,%9}, {%0,%1,%2,%3};"
        : "+f"(c[0]), "+f"(c[1]), "+f"(c[2]), "+f"(c[3])
        : "r"(a[0]), "r"(a[1]), "r"(a[2]), "r"(a[3]), "r"(b[0]), "r"(b[1]));
}
__device__ __forceinline__ uint32_t pack_bf16x2(float lo, float hi) {
    uint32_t r; asm("cvt.rn.bf16x2.f32 %0, %1, %2;" : "=r"(r) : "f"(hi), "f"(lo)); return r;
}
__device__ __forceinline__ float2 bf16x2_to_f2(uint32_t u) {
    float2 r;
    r.x = __uint_as_float(u << 16);
    r.y = __uint_as_float(u & 0xffff0000u);
    return r;
}

// ---------------- prepack: all fp32 -> bf16 hi/lo in ONE kernel -----------
#define N4_X (Msz*HIDsz/4)
#define N4_W (HIDsz*HIDsz/4)
struct alignas(8) B4 { __nv_bfloat16 v[4]; };

__global__ void __launch_bounds__(256) cvt_all_kernel(
    const float* __restrict__ x,  const float* __restrict__ qw,
    const float* __restrict__ kw, const float* __restrict__ vw,
    const float* __restrict__ ow)
{
    size_t i = (size_t)blockIdx.x * 256 + threadIdx.x;
    if (i >= (size_t)N4_X + 4*(size_t)N4_W) return;
    const float* src; __nv_bfloat16 *hi, *lo; size_t j;
    if (i < N4_X) { src = x; hi = g_xh; lo = g_xl; j = i; }
    else {
        size_t k = i - N4_X; int r = (int)(k / N4_W); j = k % N4_W;
        if (r == 0)      { src = qw; hi = g_wh;                        lo = g_wl; }
        else if (r == 1) { src = kw; hi = g_wh + (size_t)HIDsz*HIDsz;  lo = g_wl + (size_t)HIDsz*HIDsz; }
        else if (r == 2) { src = vw; hi = g_wh + 2*(size_t)HIDsz*HIDsz; lo = g_wl + 2*(size_t)HIDsz*HIDsz; }
        else             { src = ow; hi = g_owh;                       lo = g_owl; }
    }
    float4 v = ((const float4*)src)[j];
    B4 h, l;
    float xs[4] = {v.x, v.y, v.z, v.w};
    #pragma unroll
    for (int t = 0; t < 4; ++t) {
        __nv_bfloat16 hb = __float2bfloat16_rn(xs[t]);
        h.v[t] = hb;
        l.v[t] = __float2bfloat16_rn(xs[t] - __bfloat162float(hb));
    }
    *(B4*)(hi + 4*j) = h;
    *(B4*)(lo + 4*j) = l;
}

__global__ void pack_misc_kernel(const float* qb, const float* kb, const float* vb,
                                 const float* scaling)
{
    int i = blockIdx.x * 256 + threadIdx.x;
    if (i < 1024)       g_bqkv[i] = qb[i];
    else if (i < 2048)  g_bqkv[i] = kb[i-1024];
    else if (i < 3072)  g_bqkv[i] = vb[i-2048];
    if (i < 64) {
        float sc = scaling[i];
        float sp = (sc > 20.f) ? sc : log1pf(expf(sc));
        g_scale[i] = sp * (1.442695040888963f * 0.125f);
    }
}

// ---------------- HMMA GEMM mainloop (dense projections) ----------------
#define PITCH   40
#define TILE_B  (128*PITCH*2)
#define STAGE_B (4*TILE_B)
#define GEMM_SMEM (2*STAGE_B)

__device__ __forceinline__ void gemm128(
    uint32_t smem_base,
    const __nv_bfloat16* __restrict__ Ah, const __nv_bfloat16* __restrict__ Al,
    const __nv_bfloat16* __restrict__ Bh, const __nv_bfloat16* __restrict__ Bl,
    int mBase, int nBase, float acc[4][4][4])
{
    const int tid  = threadIdx.x;
    const int wid  = tid >> 5, lane = tid & 31;
    const int warpM = wid >> 2, warpN = wid & 3;

    #define LOAD_CHUNK(ch) do {                                                 \
        const int st_ = (ch) & 1; const int kt_ = (ch) * 32;                    \
        uint32_t sb_ = smem_base + st_ * STAGE_B;                               \
        _Pragma("unroll")                                                       \
        for (int t_ = 0; t_ < 4; ++t_) {                                        \
            const __nv_bfloat16* src_ = t_==0?Ah:t_==1?Al:t_==2?Bh:Bl;          \
            int rowBase_ = (t_ < 2) ? mBase : nBase;                            \
            _Pragma("unroll")                                                   \
            for (int u_ = 0; u_ < 2; ++u_) {                                    \
                int idx_ = u_*256 + tid;                                        \
                int row_ = idx_ >> 2, cc_ = idx_ & 3;                           \
                cp16(sb_ + t_*TILE_B + row_*(PITCH*2) + cc_*16,                 \
                     src_ + (size_t)(rowBase_+row_)*HIDsz + kt_ + cc_*8);       \
            }                                                                   \
        }                                                                       \
        asm volatile("cp.async.commit_group;" ::: "memory");                    \
    } while (0)

    LOAD_CHUNK(0);
    for (int ch = 0; ch < 32; ++ch) {
        if (ch < 31) {
            LOAD_CHUNK(ch+1);
            asm volatile("cp.async.wait_group 1;" ::: "memory");
        } else {
            asm volatile("cp.async.wait_group 0;" ::: "memory");
        }
        __syncthreads();
        uint32_t sb = smem_base + (ch & 1) * STAGE_B;

        #pragma unroll
        for (int ks = 0; ks < 2; ++ks) {
            uint32_t ah[4][4], al[4][4], bh[2][4], bl[2][4];
            int acol = ks*32 + 16*(lane >> 4);
            int arow = warpM*64 + (lane & 15);
            #pragma unroll
            for (int mt = 0; mt < 4; ++mt)
                ldsm4(ah[mt], sb + 0*TILE_B + (arow + mt*16)*(PITCH*2) + acol);
            #pragma unroll
            for (int mt = 0; mt < 4; ++mt)
                ldsm4(al[mt], sb + 1*TILE_B + (arow + mt*16)*(PITCH*2) + acol);
            int bcol  = ks*32 + 16*((lane >> 3) & 1);
            int brow  = warpN*32 + (lane & 7) + ((lane >> 4) << 3);
            #pragma unroll
            for (int np = 0; np < 2; ++np) {
                ldsm4(bh[np], sb + 2*TILE_B + (brow + np*16)*(PITCH*2) + bcol);
                ldsm4(bl[np], sb + 3*TILE_B + (brow + np*16)*(PITCH*2) + bcol);
            }
            #pragma unroll
            for (int mt = 0; mt < 4; ++mt)
                #pragma unroll
                for (int nt = 0; nt < 4; ++nt) {
                    const uint32_t* bhp = &bh[nt >> 1][(nt & 1) * 2];
                    const uint32_t* blp = &bl[nt >> 1][(nt & 1) * 2];
                    mma_bf16(acc[mt][nt], ah[mt], bhp);
                    mma_bf16(acc[mt][nt], al[mt], bhp);
                    mma_bf16(acc[mt][nt], ah[mt], blp);
                }
        }
        __syncthreads();
    }
    #undef LOAD_CHUNK
}

// ---------------- QKV projection (HMMA); V written transposed -------------
__global__ void __launch_bounds__(256) qkv_mma_kernel()
{
    extern __shared__ char smem[];
    uint32_t smem_base = smem_u32(smem);
    const int tid = threadIdx.x;
    const int wid = tid >> 5, lane = tid & 31;
    const int warpM = wid >> 2, warpN = wid & 3;
    const int nBase = blockIdx.x * 128;
    const int mBase = blockIdx.y * 128;

    float acc[4][4][4] = {};
    gemm128(smem_base, g_xh, g_xl, g_wh, g_wl, mBase, nBase, acc);

    const int which = nBase >> 10;

    #pragma unroll
    for (int mt = 0; mt < 4; ++mt) {
        int m0 = mBase + warpM*64 + mt*16 + (lane >> 2);
        #pragma unroll
        for (int nt = 0; nt < 4; ++nt) {
            int nG = nBase + warpN*32 + nt*8 + 2*(lane & 3);
            int nl = nG & 1023, h = nl >> 6, d = nl & 63;
            float s0 = (which == 0) ? g_scale[d] : 1.f;
            float s1 = (which == 0) ? g_scale[d+1] : 1.f;
            float b0 = g_bqkv[nG], b1 = g_bqkv[nG+1];
            #pragma unroll
            for (int half = 0; half < 2; ++half) {
                int m = m0 + half*8;
                int b = m >> 11, s = m & 2047;
                float v0 = (acc[mt][nt][half*2+0] + b0) * s0;
                float v1 = (acc[mt][nt][half*2+1] + b1) * s1;
                int bh = b*Hsz + h;
                if (which == 2) {
                    // V transposed + split: [bh][d][t]
                    __nv_bfloat16 h0 = __float2bfloat16_rn(v0);
                    __nv_bfloat16 h1 = __float2bfloat16_rn(v1);
                    __nv_bfloat16 l0 = __float2bfloat16_rn(v0 - __bfloat162float(h0));
                    __nv_bfloat16 l1 = __float2bfloat16_rn(v1 - __bfloat162float(h1));
                    size_t o0 = ((size_t)bh*Dsz + d)*Ssz + s;
                    size_t o1 = ((size_t)bh*Dsz + d + 1)*Ssz + s;
                    g_vth[o0] = h0;  g_vtl[o0] = l0;
                    g_vth[o1] = h1;  g_vtl[o1] = l1;
                } else {
                    size_t off = ((size_t)bh*Ssz + s)*Dsz + d;
                    uint32_t hh = pack_bf16x2(v0, v1);
                    float2 bb = bf16x2_to_f2(hh);
                    uint32_t ll = pack_bf16x2(v0 - bb.x, v1 - bb.y);
                    if (which == 0) {
                        *(uint32_t*)&g_qh[off] = hh;
                        *(uint32_t*)&g_ql[off] = ll;
                    } else {
                        *(uint32_t*)&g_kh[off] = hh;
                        *(uint32_t*)&g_kl[off] = ll;
                    }
                }
            }
        }
    }
}

// ---------------- HMMA flash attention tile body (two-pass, k-tile 64) ----
#define QH_OFF 0
#define QL_OFF 18432
#define ST_OFF 36864
#define ST_STRIDE 36864
#define KH_OFF 0
#define KL_OFF 9216
#define VH_OFF 18432
#define VL_OFF 27648
#define ATTN_SMEM 110592

__device__ __forceinline__ void attn_tile(
    uint32_t sb, int bh, int qb, float* attnp,
    int tid, int wid, int lane, int gid, int qc)
{
    const int qrow0 = qb * 128;
    const int ntb = 2*qb + 2;

    const __nv_bfloat16* qhg = g_qh + ((size_t)bh*Ssz + qrow0)*Dsz;
    const __nv_bfloat16* qlg = g_ql + ((size_t)bh*Ssz + qrow0)*Dsz;
    const __nv_bfloat16* khg = g_kh + (size_t)bh*Ssz*Dsz;
    const __nv_bfloat16* klg = g_kl + (size_t)bh*Ssz*Dsz;
    const __nv_bfloat16* vhg = g_vth + (size_t)bh*Dsz*Ssz;
    const __nv_bfloat16* vlg = g_vtl + (size_t)bh*Dsz*Ssz;
    float* aBase = attnp ? (attnp + (size_t)bh*Ssz*Ssz) : (float*)0;

    const int r0 = wid*16 + gid, r1 = r0 + 8;

    // Q tile + K tile 0
    #pragma unroll
    for (int u = 0; u < 4; ++u) {
        int idx = u*256 + tid, row = idx >> 3, c = idx & 7;
        cp16(sb + QH_OFF + row*144 + c*16, qhg + (size_t)row*64 + c*8);
        cp16(sb + QL_OFF + row*144 + c*16, qlg + (size_t)row*64 + c*8);
    }
    #pragma unroll
    for (int u = 0; u < 2; ++u) {
        int idx = u*256 + tid, row = idx >> 3, c = idx & 7;
        cp16(sb + ST_OFF + KH_OFF + row*144 + c*16, khg + (size_t)row*64 + c*8);
        cp16(sb + ST_OFF + KL_OFF + row*144 + c*16, klg + (size_t)row*64 + c*8);
    }
    asm volatile("cp.async.commit_group;" ::: "memory");

    float rm0 = -INFINITY, rm1 = -INFINITY, rs0 = 0.f, rs1 = 0.f;
    uint32_t qfh[4][4], qfl[4][4];

    // ================= PASS 1: stats (K only) =================
    for (int tb = 0; tb < ntb; ++tb) {
        if (tb < ntb-1) {
            const uint32_t bs2 = sb + ST_OFF + ((tb+1) & 1) * ST_STRIDE;
            const int t0 = (tb+1) * 64;
            #pragma unroll
            for (int u = 0; u < 2; ++u) {
                int idx = u*256 + tid, row = idx >> 3, c = idx & 7;
                cp16(bs2 + KH_OFF + row*144 + c*16, khg + (size_t)(t0+row)*64 + c*8);
                cp16(bs2 + KL_OFF + row*144 + c*16, klg + (size_t)(t0+row)*64 + c*8);
            }
            asm volatile("cp.async.commit_group;" ::: "memory");
            asm volatile("cp.async.wait_group 1;" ::: "memory");
        } else {
            asm volatile("cp.async.wait_group 0;" ::: "memory");
        }
        __syncthreads();

        if (tb == 0) {
            #pragma unroll
            for (int ks = 0; ks < 4; ++ks) {
                uint32_t a = sb + QH_OFF + (wid*16 + (lane & 15))*144 + ks*32 + 16*(lane >> 4);
                ldsm4(qfh[ks], a);
                ldsm4(qfl[ks], a + (QL_OFF - QH_OFF));
            }
        }
        const uint32_t bs = sb + ST_OFF + (tb & 1) * ST_STRIDE;

        float accS[8][4];
        #pragma unroll
        for (int nt = 0; nt < 8; ++nt)
            accS[nt][0] = accS[nt][1] = accS[nt][2] = accS[nt][3] = 0.f;

        #pragma unroll
        for (int ks = 0; ks < 4; ++ks) {
            uint32_t kfh[4][4], kfl[4][4];
            #pragma unroll
            for (int t4 = 0; t4 < 4; ++t4) {
                uint32_t addr = bs + KH_OFF
                    + (t4*16 + (lane & 7) + ((lane >> 4) << 3))*144
                    + ks*32 + 16*((lane >> 3) & 1);
                ldsm4(kfh[t4], addr);
                ldsm4(kfl[t4], addr + (KL_OFF - KH_OFF));
            }
            #pragma unroll
            for (int t4 = 0; t4 < 4; ++t4)
                #pragma unroll
                for (int sub = 0; sub < 2; ++sub) {
                    int nt = t4*2 + sub;
                    mma_bf16(accS[nt], qfh[ks], &kfh[t4][sub*2]);
                    mma_bf16(accS[nt], qfl[ks], &kfh[t4][sub*2]);
                    mma_bf16(accS[nt], qfh[ks], &kfl[t4][sub*2]);
                }
        }
        if (tb >= ntb-2) {
            #pragma unroll
            for (int nt = 0; nt < 8; ++nt) {
                int c0 = tb*64 + nt*8 + qc*2;
                if (c0     > qrow0 + r0) accS[nt][0] = -INFINITY;
                if (c0 + 1 > qrow0 + r0) accS[nt][1] = -INFINITY;
                if (c0     > qrow0 + r1) accS[nt][2] = -INFINITY;
                if (c0 + 1 > qrow0 + r1) accS[nt][3] = -INFINITY;
            }
        }
        float m0 = -INFINITY, m1 = -INFINITY;
        #pragma unroll
        for (int nt = 0; nt < 8; ++nt) {
            m0 = fmaxf(m0, fmaxf(accS[nt][0], accS[nt][1]));
            m1 = fmaxf(m1, fmaxf(accS[nt][2], accS[nt][3]));
        }
        m0 = fmaxf(m0, __shfl_xor_sync(0xffffffffu, m0, 1));
        m0 = fmaxf(m0, __shfl_xor_sync(0xffffffffu, m0, 2));
        m1 = fmaxf(m1, __shfl_xor_sync(0xffffffffu, m1, 1));
        m1 = fmaxf(m1, __shfl_xor_sync(0xffffffffu, m1, 2));
        float nm0 = fmaxf(rm0, m0), nm1 = fmaxf(rm1, m1);
        float f0 = __expf(rm0 - nm0), f1 = __expf(rm1 - nm1);
        float s0 = 0.f, s1 = 0.f;
        #pragma unroll
        for (int nt = 0; nt < 8; ++nt) {
            s0 += __expf(accS[nt][0] - nm0) + __expf(accS[nt][1] - nm0);
            s1 += __expf(accS[nt][2] - nm1) + __expf(accS[nt][3] - nm1);
        }
        s0 += __shfl_xor_sync(0xffffffffu, s0, 1);
        s0 += __shfl_xor_sync(0xffffffffu, s0, 2);
        s1 += __shfl_xor_sync(0xffffffffu, s1, 1);
        s1 += __shfl_xor_sync(0xffffffffu, s1, 2);
        rs0 = rs0*f0 + s0;  rs1 = rs1*f1 + s1;
        rm0 = nm0;          rm1 = nm1;
        __syncthreads();
    }

    const float inv0 = 1.f / rs0, inv1 = 1.f / rs1;
    float accO[8][4] = {};

    // prime pass-2 tile 0 (K + V)
    #pragma unroll
    for (int u = 0; u < 2; ++u) {
        int idx = u*256 + tid, row = idx >> 3, c = idx & 7;
        cp16(sb + ST_OFF + KH_OFF + row*144 + c*16, khg + (size_t)row*64 + c*8);
        cp16(sb + ST_OFF + KL_OFF + row*144 + c*16, klg + (size_t)row*64 + c*8);
    }
    #pragma unroll
    for (int u = 0; u < 2; ++u) {
        int idx = u*256 + tid, d = idx >> 3, c = idx & 7;
        cp16(sb + ST_OFF + VH_OFF + d*144 + c*16, vhg + (size_t)d*Ssz + c*8);
        cp16(sb + ST_OFF + VL_OFF + d*144 + c*16, vlg + (size_t)d*Ssz + c*8);
    }
    asm volatile("cp.async.commit_group;" ::: "memory");

    // ================= PASS 2: probs + PV =================
    for (int tb = 0; tb < ntb; ++tb) {
        if (tb < ntb-1) {
            const uint32_t bs2 = sb + ST_OFF + ((tb+1) & 1) * ST_STRIDE;
            const int t0 = (tb+1) * 64;
            #pragma unroll
            for (int u = 0; u < 2; ++u) {
                int idx = u*256 + tid, row = idx >> 3, c = idx & 7;
                cp16(bs2 + KH_OFF + row*144 + c*16, khg + (size_t)(t0+row)*64 + c*8);
                cp16(bs2 + KL_OFF + row*144 + c*16, klg + (size_t)(t0+row)*64 + c*8);
            }
            #pragma unroll
            for (int u = 0; u < 2; ++u) {
                int idx = u*256 + tid, d = idx >> 3, c = idx & 7;
                cp16(bs2 + VH_OFF + d*144 + c*16, vhg + (size_t)d*Ssz + t0 + c*8);
                cp16(bs2 + VL_OFF + d*144 + c*16, vlg + (size_t)d*Ssz + t0 + c*8);
            }
            asm volatile("cp.async.commit_group;" ::: "memory");
            asm volatile("cp.async.wait_group 1;" ::: "memory");
        } else {
            asm volatile("cp.async.wait_group 0;" ::: "memory");
        }
        __syncthreads();
        const uint32_t bs = sb + ST_OFF + (tb & 1) * ST_STRIDE;

        float accS[8][4];
        #pragma unroll
        for (int nt = 0; nt < 8; ++nt)
            accS[nt][0] = accS[nt][1] = accS[nt][2] = accS[nt][3] = 0.f;

        #pragma unroll
        for (int ks = 0; ks < 4; ++ks) {
            uint32_t kfh[4][4], kfl[4][4];
            #pragma unroll
            for (int t4 = 0; t4 < 4; ++t4) {
                uint32_t addr = bs + KH_OFF
                    + (t4*16 + (lane & 7) + ((lane >> 4) << 3))*144
                    + ks*32 + 16*((lane >> 3) & 1);
                ldsm4(kfh[t4], addr);
                ldsm4(kfl[t4], addr + (KL_OFF - KH_OFF));
            }
            #pragma unroll
            for (int t4 = 0; t4 < 4; ++t4)
                #pragma unroll
                for (int sub = 0; sub < 2; ++sub) {
                    int nt = t4*2 + sub;
                    mma_bf16(accS[nt], qfh[ks], &kfh[t4][sub*2]);
                    mma_bf16(accS[nt], qfl[ks], &kfh[t4][sub*2]);
                    mma_bf16(accS[nt], qfh[ks], &kfl[t4][sub*2]);
                }
        }
        if (tb >= ntb-2) {
            #pragma unroll
            for (int nt = 0; nt < 8; ++nt) {
                int c0 = tb*64 + nt*8 + qc*2;
                if (c0     > qrow0 + r0) accS[nt][0] = -INFINITY;
                if (c0 + 1 > qrow0 + r0) accS[nt][1] = -INFINITY;
                if (c0     > qrow0 + r1) accS[nt][2] = -INFINITY;
                if (c0 + 1 > qrow0 + r1) accS[nt][3] = -INFINITY;
            }
        }

        // final normalized probabilities
        #pragma unroll
        for (int nt = 0; nt < 8; ++nt) {
            accS[nt][0] = __expf(accS[nt][0] - rm0) * inv0;
            accS[nt][1] = __expf(accS[nt][1] - rm0) * inv0;
            accS[nt][2] = __expf(accS[nt][2] - rm1) * inv1;
            accS[nt][3] = __expf(accS[nt][3] - rm1) * inv1;
        }
        if (aBase) {
            float* rp0 = aBase + (size_t)(qrow0 + r0)*Ssz + tb*64;
            float* rp1 = rp0 + (size_t)8*Ssz;
            #pragma unroll
            for (int nt = 0; nt < 8; ++nt) {
                int col = nt*8 + qc*2;
                *(float2*)(rp0 + col) = make_float2(accS[nt][0], accS[nt][1]);
                *(float2*)(rp1 + col) = make_float2(accS[nt][2], accS[nt][3]);
            }
        }

        // O += P V (split P in registers)
        #pragma unroll
        for (int j = 0; j < 4; ++j) {
            uint32_t pah[4], pal[4];
            {
                float c0 = accS[2*j][0],   c1 = accS[2*j][1];
                float c2 = accS[2*j][2],   c3 = accS[2*j][3];
                float d0 = accS[2*j+1][0], d1 = accS[2*j+1][1];
                float d2 = accS[2*j+1][2], d3 = accS[2*j+1][3];
                pah[0] = pack_bf16x2(c0, c1);  pah[1] = pack_bf16x2(c2, c3);
                pah[2] = pack_bf16x2(d0, d1);  pah[3] = pack_bf16x2(d2, d3);
                float2 bb;
                bb = bf16x2_to_f2(pah[0]); pal[0] = pack_bf16x2(c0-bb.x, c1-bb.y);
                bb = bf16x2_to_f2(pah[1]); pal[1] = pack_bf16x2(c2-bb.x, c3-bb.y);
                bb = bf16x2_to_f2(pah[2]); pal[2] = pack_bf16x2(d0-bb.x, d1-bb.y);
                bb = bf16x2_to_f2(pah[3]); pal[3] = pack_bf16x2(d2-bb.x, d3-bb.y);
            }
            uint32_t vfh[4][4], vfl[4][4];
            #pragma unroll
            for (int np = 0; np < 4; ++np) {
                uint32_t addr = bs + VH_OFF
                    + (np*16 + (lane & 7) + ((lane >> 4) << 3))*144
                    + j*32 + 16*((lane >> 3) & 1);
                ldsm4(vfh[np], addr);
                ldsm4(vfl[np], addr + (VL_OFF - VH_OFF));
            }
            #pragma unroll
            for (int np = 0; np < 4; ++np)
                #pragma unroll
                for (int sub = 0; sub < 2; ++sub) {
                    int nd = np*2 + sub;
                    mma_bf16(accO[nd], pah, &vfh[np][sub*2]);
                    mma_bf16(accO[nd], pal, &vfh[np][sub*2]);
                    mma_bf16(accO[nd], pah, &vfl[np][sub*2]);
                }
        }
        __syncthreads();
    }

    // zero upper-triangle tiles (64-wide)
    if (aBase) {
        const float4 z4 = make_float4(0.f, 0.f, 0.f, 0.f);
        for (int tb2 = ntb; tb2 < Ssz/64; ++tb2) {
            float* tp = aBase + (size_t)qrow0*Ssz + tb2*64;
            #pragma unroll
            for (int u = 0; u < 8; ++u) {
                int idx = u*256 + tid;
                int row = idx >> 4, c = (idx & 15) << 2;
                *(float4*)(tp + (size_t)row*Ssz + c) = z4;
            }
        }
    }

    // write O as bf16 hi/lo planes (consumed directly by oproj)
    const int b = bh >> 4, h = bh & 15;
    int s0r = qrow0 + r0, s1r = qrow0 + r1;
    #pragma unroll
    for (int nd = 0; nd < 8; ++nd) {
        int d = nd*8 + qc*2;
        {
            float v0 = accO[nd][0], v1 = accO[nd][1];
            uint32_t hh = pack_bf16x2(v0, v1);
            float2 bb = bf16x2_to_f2(hh);
            uint32_t ll = pack_bf16x2(v0 - bb.x, v1 - bb.y);
            size_t off = ((size_t)(b*Ssz + s0r))*HIDsz + h*64 + d;
            *(uint32_t*)&g_aoh[off] = hh;
            *(uint32_t*)&g_aol[off] = ll;
        }
        {
            float v0 = accO[nd][2], v1 = accO[nd][3];
            uint32_t hh = pack_bf16x2(v0, v1);
            float2 bb = bf16x2_to_f2(hh);
            uint32_t ll = pack_bf16x2(v0 - bb.x, v1 - bb.y);
            size_t off = ((size_t)(b*Ssz + s1r))*HIDsz + h*64 + d;
            *(uint32_t*)&g_aoh[off] = hh;
            *(uint32_t*)&g_aol[off] = ll;
        }
    }
    __syncthreads();   // smem reuse safety between paired tiles
}

// One CTA handles a complementary pair (qb, 15-qb): uniform work of 17 units.
__global__ void __launch_bounds__(256, 2) attn_mma_kernel(float* __restrict__ attnp)
{
    extern __shared__ char sm[];
    const uint32_t sb = smem_u32(sm);
    const int tid = threadIdx.x, wid = tid >> 5, lane = tid & 31;
    const int gid = lane >> 2, qc = lane & 3;
    const int p  = blockIdx.x;          // 0..255
    const int bh = p >> 3;
    const int i  = p & 7;

    attn_tile(sb, bh, 15 - i, attnp, tid, wid, lane, gid, qc);  // heavy
    attn_tile(sb, bh, i,      attnp, tid, wid, lane, gid, qc);  // light
}

// ---------------- output projection (HMMA) ----------------
__global__ void __launch_bounds__(256) oproj_mma_kernel(
    const float* __restrict__ ob, float* __restrict__ outp)
{
    extern __shared__ char smem[];
    uint32_t smem_base = smem_u32(smem);
    const int tid = threadIdx.x;
    const int wid = tid >> 5, lane = tid & 31;
    const int warpM = wid >> 2, warpN = wid & 3;
    const int nBase = blockIdx.x * 128;
    const int mBase = blockIdx.y * 128;

    float acc[4][4][4] = {};
    gemm128(smem_base, g_aoh, g_aol, g_owh, g_owl, mBase, nBase, acc);

    #pragma unroll
    for (int mt = 0; mt < 4; ++mt) {
        int m0 = mBase + warpM*64 + mt*16 + (lane >> 2);
        #pragma unroll
        for (int nt = 0; nt < 4; ++nt) {
            int n = nBase + warpN*32 + nt*8 + 2*(lane & 3);
            float b0 = ob[n], b1 = ob[n+1];
            #pragma unroll
            for (int half = 0; half < 2; ++half) {
                int m = m0 + half*8;
                *(float2*)&outp[(size_t)m*HIDsz + n] = make_float2(
                    acc[mt][nt][half*2+0] + b0, acc[mt][nt][half*2+1] + b1);
            }
        }
    }
}

// ---------------- launch ----------------
extern "C" void kernel_launch(void* const* d_in, const int* in_sizes, int n_in,
                              void* d_out, int out_size)
{
    const float* x       = (const float*)d_in[0];
    const float* scaling = (const float*)d_in[2];
    const float* qw = (const float*)d_in[3];
    const float* qb = (const float*)d_in[4];
    const float* kw = (const float*)d_in[5];
    const float* kb = (const float*)d_in[6];
    const float* vw = (const float*)d_in[7];
    const float* vb = (const float*)d_in[8];
    const float* ow = (const float*)d_in[9];
    const float* ob = (const float*)d_in[10];

    const long long OUT_N  = (long long)Bsz*Ssz*HIDsz;
    const long long ATTN_N = (long long)Bsz*Hsz*Ssz*Ssz;

    float* outp  = (float*)d_out;
    float* attnp = 0;
    if ((long long)out_size >= OUT_N + ATTN_N) {
        attnp = (float*)d_out + OUT_N;
    } else if ((long long)out_size == ATTN_N) {
        attnp = (float*)d_out;
        void* p = 0;
        cudaGetSymbolAddress(&p, g_dummy_out);
        outp = (float*)p;
    }

    cudaFuncSetAttribute(qkv_mma_kernel, cudaFuncAttributeMaxDynamicSharedMemorySize, GEMM_SMEM);
    cudaFuncSetAttribute(oproj_mma_kernel, cudaFuncAttributeMaxDynamicSharedMemorySize, GEMM_SMEM);
    cudaFuncSetAttribute(attn_mma_kernel, cudaFuncAttributeMaxDynamicSharedMemorySize, ATTN_SMEM);

    const int NTOT = N4_X + 4*N4_W;
    cvt_all_kernel<<<(NTOT+255)/256, 256>>>(x, qw, kw, vw, ow);     // 0
    pack_misc_kernel<<<12, 256>>>(qb, kb, vb, scaling);             // 1
    qkv_mma_kernel<<<dim3(24, 32), 256, GEMM_SMEM>>>();             // 2
    attn_mma_kernel<<<256, 256, ATTN_SMEM>>>(attnp);                // 3
    oproj_mma_kernel<<<dim3(HIDsz/128, Msz/128), 256, GEMM_SMEM>>>(ob, outp); // 4
}

// round 17
// speedup vs baseline: 1.1584x; 1.0667x over previous
#include <cuda_runtime.h>
#include <cuda_bf16.h>
#include <math.h>
#include <stdint.h>

#define Bsz 2
#define Ssz 2048
#define HIDsz 1024
#define Hsz 16
#define Dsz 64
#define Msz (Bsz*Ssz)
#define BHsz (Bsz*Hsz)

// ---------------- scratch globals ----------------
__device__ float g_dummy_out[(size_t)Bsz*Ssz*HIDsz];

__device__ __nv_bfloat16 g_qh[(size_t)BHsz*Ssz*Dsz], g_ql[(size_t)BHsz*Ssz*Dsz];
__device__ __nv_bfloat16 g_kh[(size_t)BHsz*Ssz*Dsz], g_kl[(size_t)BHsz*Ssz*Dsz];
__device__ __nv_bfloat16 g_vth[(size_t)BHsz*Dsz*Ssz], g_vtl[(size_t)BHsz*Dsz*Ssz]; // [bh][d][t]

__device__ __nv_bfloat16 g_xh[(size_t)Msz*HIDsz],  g_xl[(size_t)Msz*HIDsz];
__device__ __nv_bfloat16 g_wh[(size_t)3*HIDsz*HIDsz], g_wl[(size_t)3*HIDsz*HIDsz];
__device__ __nv_bfloat16 g_owh[(size_t)HIDsz*HIDsz],  g_owl[(size_t)HIDsz*HIDsz];
__device__ __nv_bfloat16 g_aoh[(size_t)Msz*HIDsz], g_aol[(size_t)Msz*HIDsz];
__device__ float g_bqkv[3*HIDsz];
__device__ float g_scale[Dsz];

// ---------------- helpers ----------------
__device__ __forceinline__ uint32_t smem_u32(const void* p) {
    uint32_t a;
    asm("{ .reg .u64 t; cvta.to.shared.u64 t, %1; cvt.u32.u64 %0, t; }" : "=r"(a) : "l"(p));
    return a;
}
__device__ __forceinline__ void cp16(uint32_t dst, const void* src) {
    asm volatile("cp.async.cg.shared.global [%0], [%1], 16;" :: "r"(dst), "l"(src));
}
__device__ __forceinline__ void ldsm4(uint32_t* r, uint32_t a) {
    asm volatile("ldmatrix.sync.aligned.m8n8.x4.shared.b16 {%0,%1,%2,%3}, [%4];"
        : "=r"(r[0]), "=r"(r[1]), "=r"(r[2]), "=r"(r[3]) : "r"(a));
}
__device__ __forceinline__ void mma_bf16(float* c, const uint32_t* a, const uint32_t* b) {
    asm volatile("mma.sync.aligned.m16n8k16.row.col.f32.bf16.bf16.f32 "
        "{%0,%1,%2,%3}, {%4,%5,%6,%7}, {%8,%9}, {%0,%1,%2,%3};"
        : "+f"(c[0]), "+f"(c[1]), "+f"(c[2]), "+f"(c[3])
        : "r"(a[0]), "r"(a[1]), "r"(a[2]), "r"(a[3]), "r"(b[0]), "r"(b[1]));
}
__device__ __forceinline__ uint32_t pack_bf16x2(float lo, float hi) {
    uint32_t r; asm("cvt.rn.bf16x2.f32 %0, %1, %2;" : "=r"(r) : "f"(hi), "f"(lo)); return r;
}
__device__ __forceinline__ float2 bf16x2_to_f2(uint32_t u) {
    float2 r;
    r.x = __uint_as_float(u << 16);
    r.y = __uint_as_float(u & 0xffff0000u);
    return r;
}

// ---------------- prepack: all fp32 -> bf16 hi/lo in ONE kernel -----------
#define N4_X (Msz*HIDsz/4)
#define N4_W (HIDsz*HIDsz/4)
struct alignas(8) B4 { __nv_bfloat16 v[4]; };

__global__ void __launch_bounds__(256) cvt_all_kernel(
    const float* __restrict__ x,  const float* __restrict__ qw,
    const float* __restrict__ kw, const float* __restrict__ vw,
    const float* __restrict__ ow)
{
    size_t i = (size_t)blockIdx.x * 256 + threadIdx.x;
    if (i >= (size_t)N4_X + 4*(size_t)N4_W) return;
    const float* src; __nv_bfloat16 *hi, *lo; size_t j;
    if (i < N4_X) { src = x; hi = g_xh; lo = g_xl; j = i; }
    else {
        size_t k = i - N4_X; int r = (int)(k / N4_W); j = k % N4_W;
        if (r == 0)      { src = qw; hi = g_wh;                        lo = g_wl; }
        else if (r == 1) { src = kw; hi = g_wh + (size_t)HIDsz*HIDsz;  lo = g_wl + (size_t)HIDsz*HIDsz; }
        else if (r == 2) { src = vw; hi = g_wh + 2*(size_t)HIDsz*HIDsz; lo = g_wl + 2*(size_t)HIDsz*HIDsz; }
        else             { src = ow; hi = g_owh;                       lo = g_owl; }
    }
    float4 v = ((const float4*)src)[j];
    B4 h, l;
    float xs[4] = {v.x, v.y, v.z, v.w};
    #pragma unroll
    for (int t = 0; t < 4; ++t) {
        __nv_bfloat16 hb = __float2bfloat16_rn(xs[t]);
        h.v[t] = hb;
        l.v[t] = __float2bfloat16_rn(xs[t] - __bfloat162float(hb));
    }
    *(B4*)(hi + 4*j) = h;
    *(B4*)(lo + 4*j) = l;
}

__global__ void pack_misc_kernel(const float* qb, const float* kb, const float* vb,
                                 const float* scaling)
{
    int i = blockIdx.x * 256 + threadIdx.x;
    if (i < 1024)       g_bqkv[i] = qb[i];
    else if (i < 2048)  g_bqkv[i] = kb[i-1024];
    else if (i < 3072)  g_bqkv[i] = vb[i-2048];
    if (i < 64) {
        float sc = scaling[i];
        float sp = (sc > 20.f) ? sc : log1pf(expf(sc));
        g_scale[i] = sp * (1.442695040888963f * 0.125f);
    }
}

// ---------------- HMMA GEMM mainloop (dense projections) ----------------
#define PITCH   40
#define TILE_B  (128*PITCH*2)
#define STAGE_B (4*TILE_B)
#define GEMM_SMEM (2*STAGE_B)

__device__ __forceinline__ void gemm128(
    uint32_t smem_base,
    const __nv_bfloat16* __restrict__ Ah, const __nv_bfloat16* __restrict__ Al,
    const __nv_bfloat16* __restrict__ Bh, const __nv_bfloat16* __restrict__ Bl,
    int mBase, int nBase, float acc[4][4][4])
{
    const int tid  = threadIdx.x;
    const int wid  = tid >> 5, lane = tid & 31;
    const int warpM = wid >> 2, warpN = wid & 3;

    #define LOAD_CHUNK(ch) do {                                                 \
        const int st_ = (ch) & 1; const int kt_ = (ch) * 32;                    \
        uint32_t sb_ = smem_base + st_ * STAGE_B;                               \
        _Pragma("unroll")                                                       \
        for (int t_ = 0; t_ < 4; ++t_) {                                        \
            const __nv_bfloat16* src_ = t_==0?Ah:t_==1?Al:t_==2?Bh:Bl;          \
            int rowBase_ = (t_ < 2) ? mBase : nBase;                            \
            _Pragma("unroll")                                                   \
            for (int u_ = 0; u_ < 2; ++u_) {                                    \
                int idx_ = u_*256 + tid;                                        \
                int row_ = idx_ >> 2, cc_ = idx_ & 3;                           \
                cp16(sb_ + t_*TILE_B + row_*(PITCH*2) + cc_*16,                 \
                     src_ + (size_t)(rowBase_+row_)*HIDsz + kt_ + cc_*8);       \
            }                                                                   \
        }                                                                       \
        asm volatile("cp.async.commit_group;" ::: "memory");                    \
    } while (0)

    LOAD_CHUNK(0);
    for (int ch = 0; ch < 32; ++ch) {
        if (ch < 31) {
            LOAD_CHUNK(ch+1);
            asm volatile("cp.async.wait_group 1;" ::: "memory");
        } else {
            asm volatile("cp.async.wait_group 0;" ::: "memory");
        }
        __syncthreads();
        uint32_t sb = smem_base + (ch & 1) * STAGE_B;

        #pragma unroll
        for (int ks = 0; ks < 2; ++ks) {
            uint32_t ah[4][4], al[4][4], bh[2][4], bl[2][4];
            int acol = ks*32 + 16*(lane >> 4);
            int arow = warpM*64 + (lane & 15);
            #pragma unroll
            for (int mt = 0; mt < 4; ++mt)
                ldsm4(ah[mt], sb + 0*TILE_B + (arow + mt*16)*(PITCH*2) + acol);
            #pragma unroll
            for (int mt = 0; mt < 4; ++mt)
                ldsm4(al[mt], sb + 1*TILE_B + (arow + mt*16)*(PITCH*2) + acol);
            int bcol  = ks*32 + 16*((lane >> 3) & 1);
            int brow  = warpN*32 + (lane & 7) + ((lane >> 4) << 3);
            #pragma unroll
            for (int np = 0; np < 2; ++np) {
                ldsm4(bh[np], sb + 2*TILE_B + (brow + np*16)*(PITCH*2) + bcol);
                ldsm4(bl[np], sb + 3*TILE_B + (brow + np*16)*(PITCH*2) + bcol);
            }
            #pragma unroll
            for (int mt = 0; mt < 4; ++mt)
                #pragma unroll
                for (int nt = 0; nt < 4; ++nt) {
                    const uint32_t* bhp = &bh[nt >> 1][(nt & 1) * 2];
                    const uint32_t* blp = &bl[nt >> 1][(nt & 1) * 2];
                    mma_bf16(acc[mt][nt], ah[mt], bhp);
                    mma_bf16(acc[mt][nt], al[mt], bhp);
                    mma_bf16(acc[mt][nt], ah[mt], blp);
                }
        }
        __syncthreads();
    }
    #undef LOAD_CHUNK
}

// ---------------- QKV projection (HMMA); V written transposed -------------
__global__ void __launch_bounds__(256, 2) qkv_mma_kernel()
{
    extern __shared__ char smem[];
    uint32_t smem_base = smem_u32(smem);
    const int tid = threadIdx.x;
    const int wid = tid >> 5, lane = tid & 31;
    const int warpM = wid >> 2, warpN = wid & 3;
    const int nBase = blockIdx.x * 128;
    const int mBase = blockIdx.y * 128;

    float acc[4][4][4] = {};
    gemm128(smem_base, g_xh, g_xl, g_wh, g_wl, mBase, nBase, acc);

    const int which = nBase >> 10;

    #pragma unroll
    for (int mt = 0; mt < 4; ++mt) {
        int m0 = mBase + warpM*64 + mt*16 + (lane >> 2);
        #pragma unroll
        for (int nt = 0; nt < 4; ++nt) {
            int nG = nBase + warpN*32 + nt*8 + 2*(lane & 3);
            int nl = nG & 1023, h = nl >> 6, d = nl & 63;
            float s0 = (which == 0) ? g_scale[d] : 1.f;
            float s1 = (which == 0) ? g_scale[d+1] : 1.f;
            float b0 = g_bqkv[nG], b1 = g_bqkv[nG+1];
            #pragma unroll
            for (int half = 0; half < 2; ++half) {
                int m = m0 + half*8;
                int b = m >> 11, s = m & 2047;
                float v0 = (acc[mt][nt][half*2+0] + b0) * s0;
                float v1 = (acc[mt][nt][half*2+1] + b1) * s1;
                int bh = b*Hsz + h;
                if (which == 2) {
                    __nv_bfloat16 h0 = __float2bfloat16_rn(v0);
                    __nv_bfloat16 h1 = __float2bfloat16_rn(v1);
                    __nv_bfloat16 l0 = __float2bfloat16_rn(v0 - __bfloat162float(h0));
                    __nv_bfloat16 l1 = __float2bfloat16_rn(v1 - __bfloat162float(h1));
                    size_t o0 = ((size_t)bh*Dsz + d)*Ssz + s;
                    size_t o1 = ((size_t)bh*Dsz + d + 1)*Ssz + s;
                    g_vth[o0] = h0;  g_vtl[o0] = l0;
                    g_vth[o1] = h1;  g_vtl[o1] = l1;
                } else {
                    size_t off = ((size_t)bh*Ssz + s)*Dsz + d;
                    uint32_t hh = pack_bf16x2(v0, v1);
                    float2 bb = bf16x2_to_f2(hh);
                    uint32_t ll = pack_bf16x2(v0 - bb.x, v1 - bb.y);
                    if (which == 0) {
                        *(uint32_t*)&g_qh[off] = hh;
                        *(uint32_t*)&g_ql[off] = ll;
                    } else {
                        *(uint32_t*)&g_kh[off] = hh;
                        *(uint32_t*)&g_kl[off] = ll;
                    }
                }
            }
        }
    }
}

// ---------------- HMMA flash attention tile body (two-pass, k-tile 64) ----
#define QH_OFF 0
#define QL_OFF 18432
#define ST_OFF 36864
#define ST_STRIDE 36864
#define KH_OFF 0
#define KL_OFF 9216
#define VH_OFF 18432
#define VL_OFF 27648
#define ATTN_SMEM 110592

__device__ __forceinline__ void attn_tile(
    uint32_t sb, int bh, int qb, float* attnp,
    int tid, int wid, int lane, int gid, int qc)
{
    const int qrow0 = qb * 128;
    const int ntb = 2*qb + 2;

    const __nv_bfloat16* qhg = g_qh + ((size_t)bh*Ssz + qrow0)*Dsz;
    const __nv_bfloat16* qlg = g_ql + ((size_t)bh*Ssz + qrow0)*Dsz;
    const __nv_bfloat16* khg = g_kh + (size_t)bh*Ssz*Dsz;
    const __nv_bfloat16* klg = g_kl + (size_t)bh*Ssz*Dsz;
    const __nv_bfloat16* vhg = g_vth + (size_t)bh*Dsz*Ssz;
    const __nv_bfloat16* vlg = g_vtl + (size_t)bh*Dsz*Ssz;
    float* aBase = attnp ? (attnp + (size_t)bh*Ssz*Ssz) : (float*)0;

    const int r0 = wid*16 + gid, r1 = r0 + 8;

    // Q tile + K tile 0
    #pragma unroll
    for (int u = 0; u < 4; ++u) {
        int idx = u*256 + tid, row = idx >> 3, c = idx & 7;
        cp16(sb + QH_OFF + row*144 + c*16, qhg + (size_t)row*64 + c*8);
        cp16(sb + QL_OFF + row*144 + c*16, qlg + (size_t)row*64 + c*8);
    }
    #pragma unroll
    for (int u = 0; u < 2; ++u) {
        int idx = u*256 + tid, row = idx >> 3, c = idx & 7;
        cp16(sb + ST_OFF + KH_OFF + row*144 + c*16, khg + (size_t)row*64 + c*8);
        cp16(sb + ST_OFF + KL_OFF + row*144 + c*16, klg + (size_t)row*64 + c*8);
    }
    asm volatile("cp.async.commit_group;" ::: "memory");

    float rm0 = -INFINITY, rm1 = -INFINITY, rs0 = 0.f, rs1 = 0.f;
    uint32_t qfh[4][4], qfl[4][4];

    // ================= PASS 1: stats (K only) =================
    for (int tb = 0; tb < ntb; ++tb) {
        if (tb < ntb-1) {
            const uint32_t bs2 = sb + ST_OFF + ((tb+1) & 1) * ST_STRIDE;
            const int t0 = (tb+1) * 64;
            #pragma unroll
            for (int u = 0; u < 2; ++u) {
                int idx = u*256 + tid, row = idx >> 3, c = idx & 7;
                cp16(bs2 + KH_OFF + row*144 + c*16, khg + (size_t)(t0+row)*64 + c*8);
                cp16(bs2 + KL_OFF + row*144 + c*16, klg + (size_t)(t0+row)*64 + c*8);
            }
            asm volatile("cp.async.commit_group;" ::: "memory");
            asm volatile("cp.async.wait_group 1;" ::: "memory");
        } else {
            asm volatile("cp.async.wait_group 0;" ::: "memory");
        }
        __syncthreads();

        if (tb == 0) {
            #pragma unroll
            for (int ks = 0; ks < 4; ++ks) {
                uint32_t a = sb + QH_OFF + (wid*16 + (lane & 15))*144 + ks*32 + 16*(lane >> 4);
                ldsm4(qfh[ks], a);
                ldsm4(qfl[ks], a + (QL_OFF - QH_OFF));
            }
        }
        const uint32_t bs = sb + ST_OFF + (tb & 1) * ST_STRIDE;

        float accS[8][4];
        #pragma unroll
        for (int nt = 0; nt < 8; ++nt)
            accS[nt][0] = accS[nt][1] = accS[nt][2] = accS[nt][3] = 0.f;

        #pragma unroll
        for (int ks = 0; ks < 4; ++ks) {
            uint32_t kfh[4][4], kfl[4][4];
            #pragma unroll
            for (int t4 = 0; t4 < 4; ++t4) {
                uint32_t addr = bs + KH_OFF
                    + (t4*16 + (lane & 7) + ((lane >> 4) << 3))*144
                    + ks*32 + 16*((lane >> 3) & 1);
                ldsm4(kfh[t4], addr);
                ldsm4(kfl[t4], addr + (KL_OFF - KH_OFF));
            }
            #pragma unroll
            for (int t4 = 0; t4 < 4; ++t4)
                #pragma unroll
                for (int sub = 0; sub < 2; ++sub) {
                    int nt = t4*2 + sub;
                    mma_bf16(accS[nt], qfh[ks], &kfh[t4][sub*2]);
                    mma_bf16(accS[nt], qfl[ks], &kfh[t4][sub*2]);
                    mma_bf16(accS[nt], qfh[ks], &kfl[t4][sub*2]);
                }
        }
        if (tb >= ntb-2) {
            #pragma unroll
            for (int nt = 0; nt < 8; ++nt) {
                int c0 = tb*64 + nt*8 + qc*2;
                if (c0     > qrow0 + r0) accS[nt][0] = -INFINITY;
                if (c0 + 1 > qrow0 + r0) accS[nt][1] = -INFINITY;
                if (c0     > qrow0 + r1) accS[nt][2] = -INFINITY;
                if (c0 + 1 > qrow0 + r1) accS[nt][3] = -INFINITY;
            }
        }
        float m0 = -INFINITY, m1 = -INFINITY;
        #pragma unroll
        for (int nt = 0; nt < 8; ++nt) {
            m0 = fmaxf(m0, fmaxf(accS[nt][0], accS[nt][1]));
            m1 = fmaxf(m1, fmaxf(accS[nt][2], accS[nt][3]));
        }
        m0 = fmaxf(m0, __shfl_xor_sync(0xffffffffu, m0, 1));
        m0 = fmaxf(m0, __shfl_xor_sync(0xffffffffu, m0, 2));
        m1 = fmaxf(m1, __shfl_xor_sync(0xffffffffu, m1, 1));
        m1 = fmaxf(m1, __shfl_xor_sync(0xffffffffu, m1, 2));
        float nm0 = fmaxf(rm0, m0), nm1 = fmaxf(rm1, m1);
        float f0 = __expf(rm0 - nm0), f1 = __expf(rm1 - nm1);
        float s0 = 0.f, s1 = 0.f;
        #pragma unroll
        for (int nt = 0; nt < 8; ++nt) {
            s0 += __expf(accS[nt][0] - nm0) + __expf(accS[nt][1] - nm0);
            s1 += __expf(accS[nt][2] - nm1) + __expf(accS[nt][3] - nm1);
        }
        s0 += __shfl_xor_sync(0xffffffffu, s0, 1);
        s0 += __shfl_xor_sync(0xffffffffu, s0, 2);
        s1 += __shfl_xor_sync(0xffffffffu, s1, 1);
        s1 += __shfl_xor_sync(0xffffffffu, s1, 2);
        rs0 = rs0*f0 + s0;  rs1 = rs1*f1 + s1;
        rm0 = nm0;          rm1 = nm1;
        __syncthreads();
    }

    const float inv0 = 1.f / rs0, inv1 = 1.f / rs1;
    float accO[8][4] = {};

    // prime pass-2 tile 0 (K + V)
    #pragma unroll
    for (int u = 0; u < 2; ++u) {
        int idx = u*256 + tid, row = idx >> 3, c = idx & 7;
        cp16(sb + ST_OFF + KH_OFF + row*144 + c*16, khg + (size_t)row*64 + c*8);
        cp16(sb + ST_OFF + KL_OFF + row*144 + c*16, klg + (size_t)row*64 + c*8);
    }
    #pragma unroll
    for (int u = 0; u < 2; ++u) {
        int idx = u*256 + tid, d = idx >> 3, c = idx & 7;
        cp16(sb + ST_OFF + VH_OFF + d*144 + c*16, vhg + (size_t)d*Ssz + c*8);
        cp16(sb + ST_OFF + VL_OFF + d*144 + c*16, vlg + (size_t)d*Ssz + c*8);
    }
    asm volatile("cp.async.commit_group;" ::: "memory");

    // ================= PASS 2: probs + PV =================
    for (int tb = 0; tb < ntb; ++tb) {
        if (tb < ntb-1) {
            const uint32_t bs2 = sb + ST_OFF + ((tb+1) & 1) * ST_STRIDE;
            const int t0 = (tb+1) * 64;
            #pragma unroll
            for (int u = 0; u < 2; ++u) {
                int idx = u*256 + tid, row = idx >> 3, c = idx & 7;
                cp16(bs2 + KH_OFF + row*144 + c*16, khg + (size_t)(t0+row)*64 + c*8);
                cp16(bs2 + KL_OFF + row*144 + c*16, klg + (size_t)(t0+row)*64 + c*8);
            }
            #pragma unroll
            for (int u = 0; u < 2; ++u) {
                int idx = u*256 + tid, d = idx >> 3, c = idx & 7;
                cp16(bs2 + VH_OFF + d*144 + c*16, vhg + (size_t)d*Ssz + t0 + c*8);
                cp16(bs2 + VL_OFF + d*144 + c*16, vlg + (size_t)d*Ssz + t0 + c*8);
            }
            asm volatile("cp.async.commit_group;" ::: "memory");
            asm volatile("cp.async.wait_group 1;" ::: "memory");
        } else {
            asm volatile("cp.async.wait_group 0;" ::: "memory");
        }
        __syncthreads();
        const uint32_t bs = sb + ST_OFF + (tb & 1) * ST_STRIDE;

        float accS[8][4];
        #pragma unroll
        for (int nt = 0; nt < 8; ++nt)
            accS[nt][0] = accS[nt][1] = accS[nt][2] = accS[nt][3] = 0.f;

        #pragma unroll
        for (int ks = 0; ks < 4; ++ks) {
            uint32_t kfh[4][4], kfl[4][4];
            #pragma unroll
            for (int t4 = 0; t4 < 4; ++t4) {
                uint32_t addr = bs + KH_OFF
                    + (t4*16 + (lane & 7) + ((lane >> 4) << 3))*144
                    + ks*32 + 16*((lane >> 3) & 1);
                ldsm4(kfh[t4], addr);
                ldsm4(kfl[t4], addr + (KL_OFF - KH_OFF));
            }
            #pragma unroll
            for (int t4 = 0; t4 < 4; ++t4)
                #pragma unroll
                for (int sub = 0; sub < 2; ++sub) {
                    int nt = t4*2 + sub;
                    mma_bf16(accS[nt], qfh[ks], &kfh[t4][sub*2]);
                    mma_bf16(accS[nt], qfl[ks], &kfh[t4][sub*2]);
                    mma_bf16(accS[nt], qfh[ks], &kfl[t4][sub*2]);
                }
        }
        if (tb >= ntb-2) {
            #pragma unroll
            for (int nt = 0; nt < 8; ++nt) {
                int c0 = tb*64 + nt*8 + qc*2;
                if (c0     > qrow0 + r0) accS[nt][0] = -INFINITY;
                if (c0 + 1 > qrow0 + r0) accS[nt][1] = -INFINITY;
                if (c0     > qrow0 + r1) accS[nt][2] = -INFINITY;
                if (c0 + 1 > qrow0 + r1) accS[nt][3] = -INFINITY;
            }
        }

        // final normalized probabilities
        #pragma unroll
        for (int nt = 0; nt < 8; ++nt) {
            accS[nt][0] = __expf(accS[nt][0] - rm0) * inv0;
            accS[nt][1] = __expf(accS[nt][1] - rm0) * inv0;
            accS[nt][2] = __expf(accS[nt][2] - rm1) * inv1;
            accS[nt][3] = __expf(accS[nt][3] - rm1) * inv1;
        }
        if (aBase) {
            float* rp0 = aBase + (size_t)(qrow0 + r0)*Ssz + tb*64;
            float* rp1 = rp0 + (size_t)8*Ssz;
            #pragma unroll
            for (int nt = 0; nt < 8; ++nt) {
                int col = nt*8 + qc*2;
                *(float2*)(rp0 + col) = make_float2(accS[nt][0], accS[nt][1]);
                *(float2*)(rp1 + col) = make_float2(accS[nt][2], accS[nt][3]);
            }
        }

        // O += P V (split P in registers)
        #pragma unroll
        for (int j = 0; j < 4; ++j) {
            uint32_t pah[4], pal[4];
            {
                float c0 = accS[2*j][0],   c1 = accS[2*j][1];
                float c2 = accS[2*j][2],   c3 = accS[2*j][3];
                float d0 = accS[2*j+1][0], d1 = accS[2*j+1][1];
                float d2 = accS[2*j+1][2], d3 = accS[2*j+1][3];
                pah[0] = pack_bf16x2(c0, c1);  pah[1] = pack_bf16x2(c2, c3);
                pah[2] = pack_bf16x2(d0, d1);  pah[3] = pack_bf16x2(d2, d3);
                float2 bb;
                bb = bf16x2_to_f2(pah[0]); pal[0] = pack_bf16x2(c0-bb.x, c1-bb.y);
                bb = bf16x2_to_f2(pah[1]); pal[1] = pack_bf16x2(c2-bb.x, c3-bb.y);
                bb = bf16x2_to_f2(pah[2]); pal[2] = pack_bf16x2(d0-bb.x, d1-bb.y);
                bb = bf16x2_to_f2(pah[3]); pal[3] = pack_bf16x2(d2-bb.x, d3-bb.y);
            }
            uint32_t vfh[4][4], vfl[4][4];
            #pragma unroll
            for (int np = 0; np < 4; ++np) {
                uint32_t addr = bs + VH_OFF
                    + (np*16 + (lane & 7) + ((lane >> 4) << 3))*144
                    + j*32 + 16*((lane >> 3) & 1);
                ldsm4(vfh[np], addr);
                ldsm4(vfl[np], addr + (VL_OFF - VH_OFF));
            }
            #pragma unroll
            for (int np = 0; np < 4; ++np)
                #pragma unroll
                for (int sub = 0; sub < 2; ++sub) {
                    int nd = np*2 + sub;
                    mma_bf16(accO[nd], pah, &vfh[np][sub*2]);
                    mma_bf16(accO[nd], pal, &vfh[np][sub*2]);
                    mma_bf16(accO[nd], pah, &vfl[np][sub*2]);
                }
        }
        __syncthreads();
    }

    // zero upper-triangle tiles (64-wide)
    if (aBase) {
        const float4 z4 = make_float4(0.f, 0.f, 0.f, 0.f);
        for (int tb2 = ntb; tb2 < Ssz/64; ++tb2) {
            float* tp = aBase + (size_t)qrow0*Ssz + tb2*64;
            #pragma unroll
            for (int u = 0; u < 8; ++u) {
                int idx = u*256 + tid;
                int row = idx >> 4, c = (idx & 15) << 2;
                *(float4*)(tp + (size_t)row*Ssz + c) = z4;
            }
        }
    }

    // write O as bf16 hi/lo planes (consumed directly by oproj)
    const int b = bh >> 4, h = bh & 15;
    int s0r = qrow0 + r0, s1r = qrow0 + r1;
    #pragma unroll
    for (int nd = 0; nd < 8; ++nd) {
        int d = nd*8 + qc*2;
        {
            float v0 = accO[nd][0], v1 = accO[nd][1];
            uint32_t hh = pack_bf16x2(v0, v1);
            float2 bb = bf16x2_to_f2(hh);
            uint32_t ll = pack_bf16x2(v0 - bb.x, v1 - bb.y);
            size_t off = ((size_t)(b*Ssz + s0r))*HIDsz + h*64 + d;
            *(uint32_t*)&g_aoh[off] = hh;
            *(uint32_t*)&g_aol[off] = ll;
        }
        {
            float v0 = accO[nd][2], v1 = accO[nd][3];
            uint32_t hh = pack_bf16x2(v0, v1);
            float2 bb = bf16x2_to_f2(hh);
            uint32_t ll = pack_bf16x2(v0 - bb.x, v1 - bb.y);
            size_t off = ((size_t)(b*Ssz + s1r))*HIDsz + h*64 + d;
            *(uint32_t*)&g_aoh[off] = hh;
            *(uint32_t*)&g_aol[off] = ll;
        }
    }
    __syncthreads();   // smem reuse safety between chained tiles
}

// 288 uniform bins: qb=15 alone (16u), qb=14 alone (15u),
// pairs (13-g, g) for g=0..6 (15u each). Every CTA does 15-16 units.
__global__ void __launch_bounds__(256, 2) attn_mma_kernel(float* __restrict__ attnp)
{
    extern __shared__ char sm[];
    const uint32_t sb = smem_u32(sm);
    const int tid = threadIdx.x, wid = tid >> 5, lane = tid & 31;
    const int gid = lane >> 2, qc = lane & 3;
    const int c = blockIdx.x;           // 0..287

    if (c < 32) {
        attn_tile(sb, c, 15, attnp, tid, wid, lane, gid, qc);
    } else if (c < 64) {
        attn_tile(sb, c - 32, 14, attnp, tid, wid, lane, gid, qc);
    } else {
        const int g = (c - 64) >> 5;    // 0..6
        const int j = (c - 64) & 31;    // bh
        attn_tile(sb, j, 13 - g, attnp, tid, wid, lane, gid, qc);  // heavy
        attn_tile(sb, j, g,      attnp, tid, wid, lane, gid, qc);  // light
    }
}

// ---------------- output projection (HMMA) ----------------
__global__ void __launch_bounds__(256, 2) oproj_mma_kernel(
    const float* __restrict__ ob, float* __restrict__ outp)
{
    extern __shared__ char smem[];
    uint32_t smem_base = smem_u32(smem);
    const int tid = threadIdx.x;
    const int wid = tid >> 5, lane = tid & 31;
    const int warpM = wid >> 2, warpN = wid & 3;
    const int nBase = blockIdx.x * 128;
    const int mBase = blockIdx.y * 128;

    float acc[4][4][4] = {};
    gemm128(smem_base, g_aoh, g_aol, g_owh, g_owl, mBase, nBase, acc);

    #pragma unroll
    for (int mt = 0; mt < 4; ++mt) {
        int m0 = mBase + warpM*64 + mt*16 + (lane >> 2);
        #pragma unroll
        for (int nt = 0; nt < 4; ++nt) {
            int n = nBase + warpN*32 + nt*8 + 2*(lane & 3);
            float b0 = ob[n], b1 = ob[n+1];
            #pragma unroll
            for (int half = 0; half < 2; ++half) {
                int m = m0 + half*8;
                *(float2*)&outp[(size_t)m*HIDsz + n] = make_float2(
                    acc[mt][nt][half*2+0] + b0, acc[mt][nt][half*2+1] + b1);
            }
        }
    }
}

// ---------------- launch ----------------
extern "C" void kernel_launch(void* const* d_in, const int* in_sizes, int n_in,
                              void* d_out, int out_size)
{
    const float* x       = (const float*)d_in[0];
    const float* scaling = (const float*)d_in[2];
    const float* qw = (const float*)d_in[3];
    const float* qb = (const float*)d_in[4];
    const float* kw = (const float*)d_in[5];
    const float* kb = (const float*)d_in[6];
    const float* vw = (const float*)d_in[7];
    const float* vb = (const float*)d_in[8];
    const float* ow = (const float*)d_in[9];
    const float* ob = (const float*)d_in[10];

    const long long OUT_N  = (long long)Bsz*Ssz*HIDsz;
    const long long ATTN_N = (long long)Bsz*Hsz*Ssz*Ssz;

    float* outp  = (float*)d_out;
    float* attnp = 0;
    if ((long long)out_size >= OUT_N + ATTN_N) {
        attnp = (float*)d_out + OUT_N;
    } else if ((long long)out_size == ATTN_N) {
        attnp = (float*)d_out;
        void* p = 0;
        cudaGetSymbolAddress(&p, g_dummy_out);
        outp = (float*)p;
    }

    cudaFuncSetAttribute(qkv_mma_kernel, cudaFuncAttributeMaxDynamicSharedMemorySize, GEMM_SMEM);
    cudaFuncSetAttribute(oproj_mma_kernel, cudaFuncAttributeMaxDynamicSharedMemorySize, GEMM_SMEM);
    cudaFuncSetAttribute(attn_mma_kernel, cudaFuncAttributeMaxDynamicSharedMemorySize, ATTN_SMEM);

    const int NTOT = N4_X + 4*N4_W;
    cvt_all_kernel<<<(NTOT+255)/256, 256>>>(x, qw, kw, vw, ow);     // 0
    pack_misc_kernel<<<12, 256>>>(qb, kb, vb, scaling);             // 1
    qkv_mma_kernel<<<dim3(24, 32), 256, GEMM_SMEM>>>();             // 2
    attn_mma_kernel<<<288, 256, ATTN_SMEM>>>(attnp);                // 3
    oproj_mma_kernel<<<dim3(HIDsz/128, Msz/128), 256, GEMM_SMEM>>>(ob, outp); // 4
}